// round 1
// baseline (speedup 1.0000x reference)
#include <cuda_runtime.h>
#include <math.h>

#define N_ANT 64
#define HID   128
#define AP    129   // activation smem pitch (floats) - odd to kill strided bank conflicts
#define WP    132   // weight chunk pitch (floats)    - float4-aligned rows
#define SP    65    // score smem pitch
#define NTH   256

struct SmemLayout {
    float B0[N_ANT * AP];
    float B1[N_ANT * AP];
    float B2[N_ANT * AP];
    float B3[N_ANT * AP];
    float Ws[32 * WP];
    float Ss[N_ANT * SP];
    unsigned long long mb[N_ANT];
};

#define EPI_PLAIN  0
#define EPI_RELU   1
#define EPI_SIGADD 2   // C = sigmoid(acc + T)
#define EPI_TANHN  3   // C = tanh(T + R*acc)

// C[64][128] = epilogue( A[64][KDIM] @ Wg[128][KDIM]^T + bg )
// A, C, T, R are smem activation buffers (pitch AP). Wg, bg are global.
// Thread map: j0 = 4*(tid&31) (warp-lane -> 4 output cols), t0 = 8*(tid>>5) (warp -> 8 tokens).
// A reads are warp-uniform (broadcast); Ws reads are contiguous float4 (conflict-free).
template <int KDIM>
__device__ __noinline__ void gemm_full(
    const float* __restrict__ A, const float* __restrict__ Wg,
    const float* __restrict__ bg, float* __restrict__ C,
    const float* __restrict__ T, const float* __restrict__ R,
    float* __restrict__ Ws, int tid, int mode)
{
    const int lane = tid & 31;
    const int wrp  = tid >> 5;
    const int j0   = lane * 4;
    const int t0   = wrp * 8;

    float acc[8][4];
    const float4 b4 = *reinterpret_cast<const float4*>(bg + j0);
#pragma unroll
    for (int tt = 0; tt < 8; tt++) {
        acc[tt][0] = b4.x; acc[tt][1] = b4.y; acc[tt][2] = b4.z; acc[tt][3] = b4.w;
    }

#pragma unroll 1
    for (int k0 = 0; k0 < KDIM; k0 += 32) {
        __syncthreads();   // previous users of Ws are done
#pragma unroll
        for (int r = 0; r < 16; r++) {
            const int j = wrp + (r << 3);
            Ws[lane * WP + j] = Wg[j * KDIM + k0 + lane];  // coalesced LDG, transposed STS
        }
        __syncthreads();
#pragma unroll 8
        for (int kk = 0; kk < 32; kk++) {
            const float4 wv = *reinterpret_cast<const float4*>(Ws + kk * WP + j0);
#pragma unroll
            for (int tt = 0; tt < 8; tt++) {
                const float a = A[(t0 + tt) * AP + k0 + kk];  // warp-broadcast
                acc[tt][0] = fmaf(a, wv.x, acc[tt][0]);
                acc[tt][1] = fmaf(a, wv.y, acc[tt][1]);
                acc[tt][2] = fmaf(a, wv.z, acc[tt][2]);
                acc[tt][3] = fmaf(a, wv.w, acc[tt][3]);
            }
        }
    }
    __syncthreads();   // all A/Ws reads done -> safe to write C even if C aliases A

#pragma unroll
    for (int tt = 0; tt < 8; tt++) {
#pragma unroll
        for (int jj = 0; jj < 4; jj++) {
            const int idx = (t0 + tt) * AP + j0 + jj;
            float v = acc[tt][jj];
            if (mode == EPI_RELU) {
                v = fmaxf(v, 0.f);
            } else if (mode == EPI_SIGADD) {
                v += T[idx];
                v = 1.f / (1.f + __expf(-v));
            } else if (mode == EPI_TANHN) {
                v = tanhf(T[idx] + R[idx] * v);
            }
            C[idx] = v;
        }
    }
    __syncthreads();
}

// Masked MHA core: Q,K,V [64][128] in smem -> O [64][128] in smem (O may alias the
// buffer that fed the q/k/v projections; it is only written here).
__device__ __forceinline__ void attention(
    const float* __restrict__ Q, const float* __restrict__ K,
    const float* __restrict__ V, float* __restrict__ O,
    float* __restrict__ Ss, const unsigned long long* __restrict__ mb, int tid)
{
    const float scale = 0.17677669529663687f;  // 1/sqrt(32)
#pragma unroll 1
    for (int h = 0; h < 4; h++) {
        const int c0 = h * 32;
        // ---- scores: S[t][m] = scale * <q_t, k_m> ----
        {
            const int m0 = (tid & 15) * 4;
            const int t0 = (tid >> 4) * 4;
            float sa[4][4] = {};
#pragma unroll 8
            for (int d = 0; d < 32; d++) {
                float qv[4], kv[4];
#pragma unroll
                for (int i = 0; i < 4; i++) qv[i] = Q[(t0 + i) * AP + c0 + d];
#pragma unroll
                for (int i = 0; i < 4; i++) kv[i] = K[(m0 + i) * AP + c0 + d];
#pragma unroll
                for (int i = 0; i < 4; i++)
#pragma unroll
                    for (int j = 0; j < 4; j++) sa[i][j] = fmaf(qv[i], kv[j], sa[i][j]);
            }
#pragma unroll
            for (int i = 0; i < 4; i++)
#pragma unroll
                for (int j = 0; j < 4; j++) Ss[(t0 + i) * SP + m0 + j] = sa[i][j] * scale;
        }
        __syncthreads();
        // ---- masked softmax over m (4 threads per row) ----
        {
            const int t = tid >> 2;
            const int q = tid & 3;
            const unsigned long long bits = mb[t];
            float mx = -1e30f;
            for (int m = q; m < N_ANT; m += 4)
                if ((bits >> m) & 1ULL) mx = fmaxf(mx, Ss[t * SP + m]);
            mx = fmaxf(mx, __shfl_xor_sync(0xffffffffu, mx, 1));
            mx = fmaxf(mx, __shfl_xor_sync(0xffffffffu, mx, 2));
            float sum = 0.f;
            for (int m = q; m < N_ANT; m += 4) {
                const float p = ((bits >> m) & 1ULL) ? __expf(Ss[t * SP + m] - mx) : 0.f;
                Ss[t * SP + m] = p;
                sum += p;
            }
            sum += __shfl_xor_sync(0xffffffffu, sum, 1);
            sum += __shfl_xor_sync(0xffffffffu, sum, 2);
            const float rinv = 1.f / sum;
            for (int m = q; m < N_ANT; m += 4) Ss[t * SP + m] *= rinv;
        }
        __syncthreads();
        // ---- O[:, c0:c0+32] = att @ V[:, c0:c0+32] ----
        {
            const int d0 = (tid & 7) * 4;
            const int t0 = (tid >> 3) * 2;
            float oa[2][4] = {};
#pragma unroll 4
            for (int m = 0; m < N_ANT; m++) {
                const float a0 = Ss[t0 * SP + m];
                const float a1 = Ss[(t0 + 1) * SP + m];
#pragma unroll
                for (int j = 0; j < 4; j++) {
                    const float vv = V[m * AP + c0 + d0 + j];
                    oa[0][j] = fmaf(a0, vv, oa[0][j]);
                    oa[1][j] = fmaf(a1, vv, oa[1][j]);
                }
            }
#pragma unroll
            for (int i = 0; i < 2; i++)
#pragma unroll
                for (int j = 0; j < 4; j++) O[(t0 + i) * AP + c0 + d0 + j] = oa[i][j];
        }
        __syncthreads();
    }
}

__global__ void __launch_bounds__(NTH, 1) drgn_kernel(
    const float* __restrict__ x, const int* __restrict__ mask,
    const float* __restrict__ hs,
    const float* __restrict__ enc_w, const float* __restrict__ enc_b,
    const float* __restrict__ q1_w, const float* __restrict__ q1_b,
    const float* __restrict__ k1_w, const float* __restrict__ k1_b,
    const float* __restrict__ v1_w, const float* __restrict__ v1_b,
    const float* __restrict__ o1_w, const float* __restrict__ o1_b,
    const float* __restrict__ q2_w, const float* __restrict__ q2_b,
    const float* __restrict__ k2_w, const float* __restrict__ k2_b,
    const float* __restrict__ v2_w, const float* __restrict__ v2_b,
    const float* __restrict__ o2_w, const float* __restrict__ o2_b,
    const float* __restrict__ w_ih, const float* __restrict__ w_hh,
    const float* __restrict__ b_ih, const float* __restrict__ b_hh,
    const float* __restrict__ lin_w, const float* __restrict__ lin_b,
    float* __restrict__ qs_out, float* __restrict__ h3_out, int act)
{
    extern __shared__ char smem_raw[];
    SmemLayout* s = reinterpret_cast<SmemLayout*>(smem_raw);
    const int tid = threadIdx.x;
    const int b   = blockIdx.x;

    // ---- load x tile and mask bitmap ----
    {
        const float* xb = x + (size_t)b * (N_ANT * 64);
        for (int idx = tid; idx < N_ANT * 64; idx += NTH)
            s->B0[(idx >> 6) * AP + (idx & 63)] = xb[idx];
        if (tid < N_ANT) {
            const int* mrow = mask + ((size_t)b * N_ANT + tid) * N_ANT;
            unsigned long long bits = 0ULL;
            for (int m = 0; m < N_ANT; m++)
                bits |= (unsigned long long)(mrow[m] != 0) << m;
            s->mb[tid] = bits;
        }
    }
    // (gemm_full opens with __syncthreads -> orders the smem fills above)

    // ---- encoder: xe = relu(x @ enc_w^T) -> B1 ----
    gemm_full<64>(s->B0, enc_w, enc_b, s->B1, nullptr, nullptr, s->Ws, tid, EPI_RELU);

    // ---- MHA layer 1 (input xe in B1) ----
    gemm_full<128>(s->B1, q1_w, q1_b, s->B0, nullptr, nullptr, s->Ws, tid, EPI_RELU);
    gemm_full<128>(s->B1, k1_w, k1_b, s->B2, nullptr, nullptr, s->Ws, tid, EPI_RELU);
    gemm_full<128>(s->B1, v1_w, v1_b, s->B3, nullptr, nullptr, s->Ws, tid, EPI_RELU);
    attention(s->B0, s->B2, s->B3, s->B1, s->Ss, s->mb, tid);
    gemm_full<128>(s->B1, o1_w, o1_b, s->B0, nullptr, nullptr, s->Ws, tid, EPI_RELU);  // h1 -> B0

    // ---- MHA layer 2 (input h1 in B0) ----
    gemm_full<128>(s->B0, q2_w, q2_b, s->B1, nullptr, nullptr, s->Ws, tid, EPI_RELU);
    gemm_full<128>(s->B0, k2_w, k2_b, s->B2, nullptr, nullptr, s->Ws, tid, EPI_RELU);
    gemm_full<128>(s->B0, v2_w, v2_b, s->B3, nullptr, nullptr, s->Ws, tid, EPI_RELU);
    attention(s->B1, s->B2, s->B3, s->B0, s->Ss, s->mb, tid);
    gemm_full<128>(s->B0, o2_w, o2_b, s->B1, nullptr, nullptr, s->Ws, tid, EPI_RELU);  // h2 -> B1

    // ---- load previous hidden state -> B2 ----
    {
        const float* hb = hs + (size_t)b * (N_ANT * HID);
        for (int idx = tid; idx < N_ANT * HID; idx += NTH)
            s->B2[(idx >> 7) * AP + (idx & 127)] = hb[idx];
    }

    // ---- GRU cell: h2 (B1), h (B2) ----
    // r gate -> B0
    gemm_full<128>(s->B1, w_ih,             b_ih,       s->B0, nullptr, nullptr, s->Ws, tid, EPI_PLAIN);
    gemm_full<128>(s->B2, w_hh,             b_hh,       s->B0, s->B0,  nullptr, s->Ws, tid, EPI_SIGADD);
    // z gate -> B3
    gemm_full<128>(s->B1, w_ih + 128 * HID, b_ih + 128, s->B3, nullptr, nullptr, s->Ws, tid, EPI_PLAIN);
    gemm_full<128>(s->B2, w_hh + 128 * HID, b_hh + 128, s->B3, s->B3,  nullptr, s->Ws, tid, EPI_SIGADD);
    // n gate: i_n -> B1 (in place over h2, safe: gemm syncs before epilogue writes)
    gemm_full<128>(s->B1, w_ih + 256 * HID, b_ih + 256, s->B1, nullptr, nullptr, s->Ws, tid, EPI_PLAIN);
    gemm_full<128>(s->B2, w_hh + 256 * HID, b_hh + 256, s->B1, s->B1,  s->B0,   s->Ws, tid, EPI_TANHN);

    // ---- h3 = (1-z)*n + z*h ; write h3 to gmem and keep in B1 ----
    {
        float* h3b = h3_out + (size_t)b * (N_ANT * HID);
        for (int idx = tid; idx < N_ANT * HID; idx += NTH) {
            const int off = (idx >> 7) * AP + (idx & 127);
            const float z  = s->B3[off];
            const float h3 = (1.f - z) * s->B1[off] + z * s->B2[off];
            s->B1[off] = h3;
            h3b[idx]   = h3;
        }
    }
    __syncthreads();

    // ---- qs = h3 @ lin_w^T + lin_b ----
    {
        float* qb = qs_out + (size_t)b * (N_ANT * act);
        for (int idx = tid; idx < N_ANT * act; idx += NTH) {
            const int t = idx / act;
            const int a = idx - t * act;
            const float* wr = lin_w + a * HID;
            float sacc = lin_b[a];
#pragma unroll 8
            for (int k = 0; k < HID; k++) sacc = fmaf(s->B1[t * AP + k], wr[k], sacc);
            qb[idx] = sacc;
        }
    }
}

extern "C" void kernel_launch(void* const* d_in, const int* in_sizes, int n_in,
                              void* d_out, int out_size)
{
    const float* x     = (const float*)d_in[0];
    const int*   mask  = (const int*)  d_in[1];
    const float* hs    = (const float*)d_in[2];
    const float* enc_w = (const float*)d_in[3];
    const float* enc_b = (const float*)d_in[4];
    const float* q1_w  = (const float*)d_in[5];
    const float* q1_b  = (const float*)d_in[6];
    const float* k1_w  = (const float*)d_in[7];
    const float* k1_b  = (const float*)d_in[8];
    const float* v1_w  = (const float*)d_in[9];
    const float* v1_b  = (const float*)d_in[10];
    const float* o1_w  = (const float*)d_in[11];
    const float* o1_b  = (const float*)d_in[12];
    const float* q2_w  = (const float*)d_in[13];
    const float* q2_b  = (const float*)d_in[14];
    const float* k2_w  = (const float*)d_in[15];
    const float* k2_b  = (const float*)d_in[16];
    const float* v2_w  = (const float*)d_in[17];
    const float* v2_b  = (const float*)d_in[18];
    const float* o2_w  = (const float*)d_in[19];
    const float* o2_b  = (const float*)d_in[20];
    const float* w_ih  = (const float*)d_in[21];
    const float* w_hh  = (const float*)d_in[22];
    const float* b_ih  = (const float*)d_in[23];
    const float* b_hh  = (const float*)d_in[24];
    const float* lin_w = (const float*)d_in[25];
    const float* lin_b = (const float*)d_in[26];

    const int bs  = in_sizes[0] / (N_ANT * 64);
    const int act = in_sizes[25] / HID;  // 20

    float* qs = (float*)d_out;
    float* h3 = qs + (size_t)bs * N_ANT * act;

    const int smem_bytes = (int)sizeof(SmemLayout);
    cudaFuncSetAttribute(drgn_kernel, cudaFuncAttributeMaxDynamicSharedMemorySize, smem_bytes);

    drgn_kernel<<<bs, NTH, smem_bytes>>>(
        x, mask, hs, enc_w, enc_b,
        q1_w, q1_b, k1_w, k1_b, v1_w, v1_b, o1_w, o1_b,
        q2_w, q2_b, k2_w, k2_b, v2_w, v2_b, o2_w, o2_b,
        w_ih, w_hh, b_ih, b_hh, lin_w, lin_b,
        qs, h3, act);
}

// round 2
// speedup vs baseline: 1.1337x; 1.1337x over previous
#include <cuda_runtime.h>
#include <math.h>

#define N_ANT 64
#define HID   128
#define AP    132   // activation pitch (floats): multiple of 4 -> LDS.128-able rows
#define WP    132   // staged-weight pitch
#define SP    65    // score pitch
#define NTH   256

typedef unsigned long long u64;

__device__ __forceinline__ u64 pack2(float lo, float hi) {
    u64 r; asm("mov.b64 %0,{%1,%2};" : "=l"(r) : "f"(lo), "f"(hi)); return r;
}
__device__ __forceinline__ u64 dup2(float v) { return pack2(v, v); }
__device__ __forceinline__ u64 ffma2(u64 a, u64 b, u64 c) {
    u64 d; asm("fma.rn.f32x2 %0,%1,%2,%3;" : "=l"(d) : "l"(a), "l"(b), "l"(c)); return d;
}
__device__ __forceinline__ float2 unpack2(u64 p) {
    float2 f; asm("mov.b64 {%0,%1},%2;" : "=f"(f.x), "=f"(f.y) : "l"(p)); return f;
}

struct __align__(16) SmemLayout {
    float B0[N_ANT * AP];
    float B1[N_ANT * AP];
    float B2[N_ANT * AP];
    float B3[N_ANT * AP];
    float Ws[32 * WP];
    float Ss[N_ANT * SP];
    unsigned long long mb[N_ANT];
};

#define EPI_PLAIN  0
#define EPI_RELU   1
#define EPI_SIGADD 2   // C = sigmoid(acc + T)
#define EPI_TANHN  3   // C = tanh(T + R*acc)

// ---- weight chunk staging: 32 k x 128 j, 2-way-conflict STS, coalesced-enough LDG ----
template <int KDIM>
__device__ __forceinline__ void ldg_chunk(const float* __restrict__ Wg, int k0,
                                          int tid, float4 w[4]) {
    const int j  = tid >> 1;
    const int kq = tid & 1;
    const float* src = Wg + j * KDIM + k0 + kq * 16;
#pragma unroll
    for (int c = 0; c < 4; c++)
        w[c] = *reinterpret_cast<const float4*>(src + c * 4);
}
__device__ __forceinline__ void sts_chunk(float* __restrict__ Ws, int tid, const float4 w[4]) {
    const int j  = tid >> 1;
    const int kb = (tid & 1) * 16;
#pragma unroll
    for (int c = 0; c < 4; c++) {
        Ws[(kb + 4 * c + 0) * WP + j] = w[c].x;
        Ws[(kb + 4 * c + 1) * WP + j] = w[c].y;
        Ws[(kb + 4 * c + 2) * WP + j] = w[c].z;
        Ws[(kb + 4 * c + 3) * WP + j] = w[c].w;
    }
}

// C[64][128] = epilogue( A[64][KDIM] @ Wg[128][KDIM]^T + bg )
// lane -> 4 output cols (j0=4*lane), warp -> 8 tokens (t0=8*warp).
// f32x2 packed accumulation: acc2[t][0]=(j0,j0+1), acc2[t][1]=(j0+2,j0+3).
template <int KDIM>
__device__ __noinline__ void gemm_full(
    const float* __restrict__ A, const float* __restrict__ Wg,
    const float* __restrict__ bg, float* __restrict__ C,
    const float* __restrict__ T, const float* __restrict__ R,
    float* __restrict__ Ws, int tid, int mode)
{
    const int lane = tid & 31;
    const int wrp  = tid >> 5;
    const int j0   = lane * 4;
    const int t0   = wrp * 8;

    u64 acc2[8][2];
    {
        const float4 b4 = *reinterpret_cast<const float4*>(bg + j0);
        const u64 b01 = pack2(b4.x, b4.y);
        const u64 b23 = pack2(b4.z, b4.w);
#pragma unroll
        for (int t = 0; t < 8; t++) { acc2[t][0] = b01; acc2[t][1] = b23; }
    }

    float4 wst[4];
    ldg_chunk<KDIM>(Wg, 0, tid, wst);
    constexpr int NC = KDIM / 32;

#pragma unroll 1
    for (int c = 0; c < NC; c++) {
        __syncthreads();                 // previous users of Ws done
        sts_chunk(Ws, tid, wst);
        __syncthreads();
        if (c + 1 < NC) ldg_chunk<KDIM>(Wg, (c + 1) * 32, tid, wst);  // prefetch under compute
        const int k0 = c * 32;
#pragma unroll 2
        for (int kb = 0; kb < 8; kb++) {
            float4 a4[8];
#pragma unroll
            for (int t = 0; t < 8; t++)
                a4[t] = *reinterpret_cast<const float4*>(A + (t0 + t) * AP + k0 + kb * 4);
#pragma unroll
            for (int q = 0; q < 4; q++) {
                const float4 wv = *reinterpret_cast<const float4*>(Ws + (kb * 4 + q) * WP + j0);
                const u64 w01 = pack2(wv.x, wv.y);
                const u64 w23 = pack2(wv.z, wv.w);
#pragma unroll
                for (int t = 0; t < 8; t++) {
                    const float av = (q == 0) ? a4[t].x : (q == 1) ? a4[t].y
                                   : (q == 2) ? a4[t].z : a4[t].w;
                    const u64 ad = dup2(av);
                    acc2[t][0] = ffma2(ad, w01, acc2[t][0]);
                    acc2[t][1] = ffma2(ad, w23, acc2[t][1]);
                }
            }
        }
    }
    __syncthreads();   // all A/Ws reads done -> safe to write C even if C aliases A

#pragma unroll
    for (int t = 0; t < 8; t++) {
        const int idx = (t0 + t) * AP + j0;
        const float2 v01 = unpack2(acc2[t][0]);
        const float2 v23 = unpack2(acc2[t][1]);
        float v[4] = {v01.x, v01.y, v23.x, v23.y};
        if (mode == EPI_RELU) {
#pragma unroll
            for (int j = 0; j < 4; j++) v[j] = fmaxf(v[j], 0.f);
        } else if (mode == EPI_SIGADD) {
            const float4 t4 = *reinterpret_cast<const float4*>(T + idx);
            v[0] += t4.x; v[1] += t4.y; v[2] += t4.z; v[3] += t4.w;
#pragma unroll
            for (int j = 0; j < 4; j++) v[j] = 1.f / (1.f + __expf(-v[j]));
        } else if (mode == EPI_TANHN) {
            const float4 t4 = *reinterpret_cast<const float4*>(T + idx);
            const float4 r4 = *reinterpret_cast<const float4*>(R + idx);
            v[0] = tanhf(t4.x + r4.x * v[0]);
            v[1] = tanhf(t4.y + r4.y * v[1]);
            v[2] = tanhf(t4.z + r4.z * v[2]);
            v[3] = tanhf(t4.w + r4.w * v[3]);
        }
        float4 o4 = make_float4(v[0], v[1], v[2], v[3]);
        *reinterpret_cast<float4*>(C + idx) = o4;
    }
    __syncthreads();
}

// Masked MHA core.
__device__ __noinline__ void attention(
    const float* __restrict__ Q, const float* __restrict__ K,
    const float* __restrict__ V, float* __restrict__ O,
    float* __restrict__ Ss, const unsigned long long* __restrict__ mb, int tid)
{
    const float scale = 0.17677669529663687f;  // 1/sqrt(32)
    const int lane = tid & 31;
    const int wrp  = tid >> 5;
#pragma unroll 1
    for (int h = 0; h < 4; h++) {
        const int c0 = h * 32;
        // ---- scores: lane -> m in {lane, lane+32}; warp -> tokens t0..t0+7 ----
        {
            const int t0 = wrp * 8;
            u64 acc[4][2];
#pragma unroll
            for (int tp = 0; tp < 4; tp++) { acc[tp][0] = 0ULL; acc[tp][1] = 0ULL; }
#pragma unroll 2
            for (int d0 = 0; d0 < 32; d0 += 4) {
                const float4 kl4 = *reinterpret_cast<const float4*>(K + lane * AP + c0 + d0);
                const float4 kh4 = *reinterpret_cast<const float4*>(K + (lane + 32) * AP + c0 + d0);
                float4 q4[8];
#pragma unroll
                for (int t = 0; t < 8; t++)
                    q4[t] = *reinterpret_cast<const float4*>(Q + (t0 + t) * AP + c0 + d0);
#pragma unroll
                for (int d = 0; d < 4; d++) {
                    const float klv = (d == 0) ? kl4.x : (d == 1) ? kl4.y : (d == 2) ? kl4.z : kl4.w;
                    const float khv = (d == 0) ? kh4.x : (d == 1) ? kh4.y : (d == 2) ? kh4.z : kh4.w;
                    const u64 kl = dup2(klv);
                    const u64 kh = dup2(khv);
#pragma unroll
                    for (int tp = 0; tp < 4; tp++) {
                        const float qe = (d == 0) ? q4[2 * tp].x : (d == 1) ? q4[2 * tp].y
                                       : (d == 2) ? q4[2 * tp].z : q4[2 * tp].w;
                        const float qo = (d == 0) ? q4[2 * tp + 1].x : (d == 1) ? q4[2 * tp + 1].y
                                       : (d == 2) ? q4[2 * tp + 1].z : q4[2 * tp + 1].w;
                        const u64 q2 = pack2(qe, qo);
                        acc[tp][0] = ffma2(q2, kl, acc[tp][0]);
                        acc[tp][1] = ffma2(q2, kh, acc[tp][1]);
                    }
                }
            }
#pragma unroll
            for (int tp = 0; tp < 4; tp++) {
                const float2 lo = unpack2(acc[tp][0]);
                const float2 hi = unpack2(acc[tp][1]);
                Ss[(t0 + 2 * tp) * SP + lane]          = lo.x * scale;
                Ss[(t0 + 2 * tp + 1) * SP + lane]      = lo.y * scale;
                Ss[(t0 + 2 * tp) * SP + lane + 32]     = hi.x * scale;
                Ss[(t0 + 2 * tp + 1) * SP + lane + 32] = hi.y * scale;
            }
        }
        __syncthreads();
        // ---- masked softmax over m (4 threads per row) ----
        {
            const int t = tid >> 2;
            const int q = tid & 3;
            const unsigned long long bits = mb[t];
            float mx = -1e30f;
            for (int m = q; m < N_ANT; m += 4)
                if ((bits >> m) & 1ULL) mx = fmaxf(mx, Ss[t * SP + m]);
            mx = fmaxf(mx, __shfl_xor_sync(0xffffffffu, mx, 1));
            mx = fmaxf(mx, __shfl_xor_sync(0xffffffffu, mx, 2));
            float sum = 0.f;
            for (int m = q; m < N_ANT; m += 4) {
                const float p = ((bits >> m) & 1ULL) ? __expf(Ss[t * SP + m] - mx) : 0.f;
                Ss[t * SP + m] = p;
                sum += p;
            }
            sum += __shfl_xor_sync(0xffffffffu, sum, 1);
            sum += __shfl_xor_sync(0xffffffffu, sum, 2);
            const float rinv = 1.f / sum;
            for (int m = q; m < N_ANT; m += 4) Ss[t * SP + m] *= rinv;
        }
        __syncthreads();
        // ---- O[:, c0:c0+32] = att @ V[:, c0:c0+32] ----
        {
            const int d0 = (tid & 7) * 4;
            const int t0 = (tid >> 3) * 2;
            u64 oa[2][2] = {{0ULL, 0ULL}, {0ULL, 0ULL}};
#pragma unroll 4
            for (int m = 0; m < N_ANT; m++) {
                const float4 vv = *reinterpret_cast<const float4*>(V + m * AP + c0 + d0);
                const u64 v01 = pack2(vv.x, vv.y);
                const u64 v23 = pack2(vv.z, vv.w);
                const u64 a0 = dup2(Ss[t0 * SP + m]);
                const u64 a1 = dup2(Ss[(t0 + 1) * SP + m]);
                oa[0][0] = ffma2(a0, v01, oa[0][0]);
                oa[0][1] = ffma2(a0, v23, oa[0][1]);
                oa[1][0] = ffma2(a1, v01, oa[1][0]);
                oa[1][1] = ffma2(a1, v23, oa[1][1]);
            }
#pragma unroll
            for (int i = 0; i < 2; i++) {
                const float2 o01 = unpack2(oa[i][0]);
                const float2 o23 = unpack2(oa[i][1]);
                *reinterpret_cast<float4*>(O + (t0 + i) * AP + c0 + d0) =
                    make_float4(o01.x, o01.y, o23.x, o23.y);
            }
        }
        __syncthreads();
    }
}

__global__ void __launch_bounds__(NTH, 1) drgn_kernel(
    const float* __restrict__ x, const int* __restrict__ mask,
    const float* __restrict__ hs,
    const float* __restrict__ enc_w, const float* __restrict__ enc_b,
    const float* __restrict__ q1_w, const float* __restrict__ q1_b,
    const float* __restrict__ k1_w, const float* __restrict__ k1_b,
    const float* __restrict__ v1_w, const float* __restrict__ v1_b,
    const float* __restrict__ o1_w, const float* __restrict__ o1_b,
    const float* __restrict__ q2_w, const float* __restrict__ q2_b,
    const float* __restrict__ k2_w, const float* __restrict__ k2_b,
    const float* __restrict__ v2_w, const float* __restrict__ v2_b,
    const float* __restrict__ o2_w, const float* __restrict__ o2_b,
    const float* __restrict__ w_ih, const float* __restrict__ w_hh,
    const float* __restrict__ b_ih, const float* __restrict__ b_hh,
    const float* __restrict__ lin_w, const float* __restrict__ lin_b,
    float* __restrict__ qs_out, float* __restrict__ h3_out, int act)
{
    extern __shared__ char smem_raw[];
    SmemLayout* s = reinterpret_cast<SmemLayout*>(smem_raw);
    const int tid = threadIdx.x;
    const int b   = blockIdx.x;

    // ---- load x tile and mask bitmap ----
    {
        const float* xb = x + (size_t)b * (N_ANT * 64);
        for (int idx = tid; idx < N_ANT * 64; idx += NTH)
            s->B0[(idx >> 6) * AP + (idx & 63)] = xb[idx];
        if (tid < N_ANT) {
            const int* mrow = mask + ((size_t)b * N_ANT + tid) * N_ANT;
            unsigned long long bits = 0ULL;
            for (int m = 0; m < N_ANT; m++)
                bits |= (unsigned long long)(mrow[m] != 0) << m;
            s->mb[tid] = bits;
        }
    }
    // (gemm_full's first __syncthreads orders the fills above before Ws reuse;
    //  A reads happen after that barrier too)

    // ---- encoder: xe = relu(x @ enc_w^T) -> B1 ----
    gemm_full<64>(s->B0, enc_w, enc_b, s->B1, nullptr, nullptr, s->Ws, tid, EPI_RELU);

    // ---- MHA layer 1 (input xe in B1) ----
    gemm_full<128>(s->B1, q1_w, q1_b, s->B0, nullptr, nullptr, s->Ws, tid, EPI_RELU);
    gemm_full<128>(s->B1, k1_w, k1_b, s->B2, nullptr, nullptr, s->Ws, tid, EPI_RELU);
    gemm_full<128>(s->B1, v1_w, v1_b, s->B3, nullptr, nullptr, s->Ws, tid, EPI_RELU);
    attention(s->B0, s->B2, s->B3, s->B1, s->Ss, s->mb, tid);
    gemm_full<128>(s->B1, o1_w, o1_b, s->B0, nullptr, nullptr, s->Ws, tid, EPI_RELU);  // h1 -> B0

    // ---- MHA layer 2 (input h1 in B0) ----
    gemm_full<128>(s->B0, q2_w, q2_b, s->B1, nullptr, nullptr, s->Ws, tid, EPI_RELU);
    gemm_full<128>(s->B0, k2_w, k2_b, s->B2, nullptr, nullptr, s->Ws, tid, EPI_RELU);
    gemm_full<128>(s->B0, v2_w, v2_b, s->B3, nullptr, nullptr, s->Ws, tid, EPI_RELU);
    attention(s->B1, s->B2, s->B3, s->B0, s->Ss, s->mb, tid);
    gemm_full<128>(s->B0, o2_w, o2_b, s->B1, nullptr, nullptr, s->Ws, tid, EPI_RELU);  // h2 -> B1

    // ---- load previous hidden state -> B2 ----
    {
        const float* hb = hs + (size_t)b * (N_ANT * HID);
        for (int idx = tid; idx < N_ANT * HID; idx += NTH)
            s->B2[(idx >> 7) * AP + (idx & 127)] = hb[idx];
    }

    // ---- GRU cell: h2 (B1), h (B2) ----
    gemm_full<128>(s->B1, w_ih,             b_ih,       s->B0, nullptr, nullptr, s->Ws, tid, EPI_PLAIN);
    gemm_full<128>(s->B2, w_hh,             b_hh,       s->B0, s->B0,  nullptr, s->Ws, tid, EPI_SIGADD);
    gemm_full<128>(s->B1, w_ih + 128 * HID, b_ih + 128, s->B3, nullptr, nullptr, s->Ws, tid, EPI_PLAIN);
    gemm_full<128>(s->B2, w_hh + 128 * HID, b_hh + 128, s->B3, s->B3,  nullptr, s->Ws, tid, EPI_SIGADD);
    gemm_full<128>(s->B1, w_ih + 256 * HID, b_ih + 256, s->B1, nullptr, nullptr, s->Ws, tid, EPI_PLAIN);
    gemm_full<128>(s->B2, w_hh + 256 * HID, b_hh + 256, s->B1, s->B1,  s->B0,   s->Ws, tid, EPI_TANHN);

    // ---- h3 = (1-z)*n + z*h ; write h3 to gmem and keep in B1 ----
    {
        float* h3b = h3_out + (size_t)b * (N_ANT * HID);
        for (int idx = tid; idx < N_ANT * HID; idx += NTH) {
            const int off = (idx >> 7) * AP + (idx & 127);
            const float z  = s->B3[off];
            const float h3 = (1.f - z) * s->B1[off] + z * s->B2[off];
            s->B1[off] = h3;
            h3b[idx]   = h3;
        }
    }
    __syncthreads();

    // ---- qs = h3 @ lin_w^T + lin_b ----
    {
        float* qb = qs_out + (size_t)b * (N_ANT * act);
        for (int idx = tid; idx < N_ANT * act; idx += NTH) {
            const int t = idx / act;
            const int a = idx - t * act;
            const float* wr = lin_w + a * HID;
            float sacc = lin_b[a];
#pragma unroll 8
            for (int k = 0; k < HID; k++) sacc = fmaf(s->B1[t * AP + k], wr[k], sacc);
            qb[idx] = sacc;
        }
    }
}

extern "C" void kernel_launch(void* const* d_in, const int* in_sizes, int n_in,
                              void* d_out, int out_size)
{
    const float* x     = (const float*)d_in[0];
    const int*   mask  = (const int*)  d_in[1];
    const float* hs    = (const float*)d_in[2];
    const float* enc_w = (const float*)d_in[3];
    const float* enc_b = (const float*)d_in[4];
    const float* q1_w  = (const float*)d_in[5];
    const float* q1_b  = (const float*)d_in[6];
    const float* k1_w  = (const float*)d_in[7];
    const float* k1_b  = (const float*)d_in[8];
    const float* v1_w  = (const float*)d_in[9];
    const float* v1_b  = (const float*)d_in[10];
    const float* o1_w  = (const float*)d_in[11];
    const float* o1_b  = (const float*)d_in[12];
    const float* q2_w  = (const float*)d_in[13];
    const float* q2_b  = (const float*)d_in[14];
    const float* k2_w  = (const float*)d_in[15];
    const float* k2_b  = (const float*)d_in[16];
    const float* v2_w  = (const float*)d_in[17];
    const float* v2_b  = (const float*)d_in[18];
    const float* o2_w  = (const float*)d_in[19];
    const float* o2_b  = (const float*)d_in[20];
    const float* w_ih  = (const float*)d_in[21];
    const float* w_hh  = (const float*)d_in[22];
    const float* b_ih  = (const float*)d_in[23];
    const float* b_hh  = (const float*)d_in[24];
    const float* lin_w = (const float*)d_in[25];
    const float* lin_b = (const float*)d_in[26];

    const int bs  = in_sizes[0] / (N_ANT * 64);
    const int act = in_sizes[25] / HID;  // 20

    float* qs = (float*)d_out;
    float* h3 = qs + (size_t)bs * N_ANT * act;

    const int smem_bytes = (int)sizeof(SmemLayout);
    cudaFuncSetAttribute(drgn_kernel, cudaFuncAttributeMaxDynamicSharedMemorySize, smem_bytes);

    drgn_kernel<<<bs, NTH, smem_bytes>>>(
        x, mask, hs, enc_w, enc_b,
        q1_w, q1_b, k1_w, k1_b, v1_w, v1_b, o1_w, o1_b,
        q2_w, q2_b, k2_w, k2_b, v2_w, v2_b, o2_w, o2_b,
        w_ih, w_hh, b_ih, b_hh, lin_w, lin_b,
        qs, h3, act);
}